// round 1
// baseline (speedup 1.0000x reference)
#include <cuda_runtime.h>

// Problem constants
#define BSZ 8
#define SEQ 1024
#define NX  1024
#define NH  16
#define HD  64

#define GELEMS (8u * 1024u * 1024u)  // 8*1024*1024 floats per scratch buffer

__device__ float g_q[GELEMS];
__device__ float g_k[GELEMS];
__device__ float g_v[GELEMS];
__device__ float g_a[GELEMS];

// ---------------------------------------------------------------------------
// SGEMM with fused bias: C[M,N] = A[M,K] @ W[K,:] (+ bias), fp32
// A row-major lda=K; W row-major ldw (pointer pre-offset to the desired
// column block); C row-major ldc. All dims multiples of tile sizes.
// 128x128x16 tile, 256 threads, 8x8 per-thread micro-tile.
// ---------------------------------------------------------------------------
__global__ __launch_bounds__(256) void sgemm_bias_kernel(
    const float* __restrict__ A, const float* __restrict__ W,
    const float* __restrict__ bias, float* __restrict__ C,
    int M, int N, int K, int ldw, int ldc)
{
    __shared__ float As[16][128];   // transposed: As[k][m]
    __shared__ float Bs[16][132];   // Bs[k][n], padded

    const int tid = threadIdx.x;
    const int tx = tid & 15;
    const int ty = tid >> 4;
    const int m0 = blockIdx.y * 128;
    const int n0 = blockIdx.x * 128;

    // A-tile load mapping: each thread loads row a_row, cols ac..ac+7 (two float4)
    const int a_row = tid >> 1;
    const int ac    = (tid & 1) * 8;
    // B-tile load mapping: row b_row, cols b_col..b_col+7
    const int b_row = tid >> 4;
    const int b_col = (tid & 15) * 8;

    const float* Aptr = A + (long)(m0 + a_row) * K;

    float acc[8][8];
#pragma unroll
    for (int i = 0; i < 8; ++i)
#pragma unroll
        for (int j = 0; j < 8; ++j) acc[i][j] = 0.0f;

    for (int k0 = 0; k0 < K; k0 += 16) {
        float4 a0 = *(const float4*)(Aptr + k0 + ac);
        float4 a1 = *(const float4*)(Aptr + k0 + ac + 4);
        const float* Wp = W + (long)(k0 + b_row) * ldw + n0 + b_col;
        float4 b0 = *(const float4*)(Wp);
        float4 b1 = *(const float4*)(Wp + 4);

        __syncthreads();
        As[ac + 0][a_row] = a0.x; As[ac + 1][a_row] = a0.y;
        As[ac + 2][a_row] = a0.z; As[ac + 3][a_row] = a0.w;
        As[ac + 4][a_row] = a1.x; As[ac + 5][a_row] = a1.y;
        As[ac + 6][a_row] = a1.z; As[ac + 7][a_row] = a1.w;
        *(float4*)&Bs[b_row][b_col]     = b0;
        *(float4*)&Bs[b_row][b_col + 4] = b1;
        __syncthreads();

#pragma unroll
        for (int kk = 0; kk < 16; ++kk) {
            float4 x0 = *(const float4*)&As[kk][ty * 8];
            float4 x1 = *(const float4*)&As[kk][ty * 8 + 4];
            float4 y0 = *(const float4*)&Bs[kk][tx * 8];
            float4 y1 = *(const float4*)&Bs[kk][tx * 8 + 4];
            float av[8] = {x0.x, x0.y, x0.z, x0.w, x1.x, x1.y, x1.z, x1.w};
            float bv[8] = {y0.x, y0.y, y0.z, y0.w, y1.x, y1.y, y1.z, y1.w};
#pragma unroll
            for (int i = 0; i < 8; ++i)
#pragma unroll
                for (int j = 0; j < 8; ++j)
                    acc[i][j] = fmaf(av[i], bv[j], acc[i][j]);
        }
    }

    // Epilogue: add bias, store
    float bvv[8];
#pragma unroll
    for (int j = 0; j < 8; ++j) bvv[j] = bias[n0 + tx * 8 + j];

#pragma unroll
    for (int i = 0; i < 8; ++i) {
        float* Cp = C + (long)(m0 + ty * 8 + i) * ldc + n0 + tx * 8;
        float4 c0 = make_float4(acc[i][0] + bvv[0], acc[i][1] + bvv[1],
                                acc[i][2] + bvv[2], acc[i][3] + bvv[3]);
        float4 c1 = make_float4(acc[i][4] + bvv[4], acc[i][5] + bvv[5],
                                acc[i][6] + bvv[6], acc[i][7] + bvv[7]);
        *(float4*)(Cp)     = c0;
        *(float4*)(Cp + 4) = c1;
    }
}

// ---------------------------------------------------------------------------
// Flash attention, fp32. q/k/v scratch layout: [B, S, H, HD] == [m, NX]
// (i.e., element (b,s,h,d) at (b*S+s)*NX + h*HD + d).
// Grid: (S/BQ, H, B). Block: 128 threads, each an 8x8 micro-tile.
// BQ=128 query rows per CTA, BK=64 key cols per inner block.
// Causal: k-blocks strictly above diagonal are skipped.
// ---------------------------------------------------------------------------
#define BQ 128
#define BK 64
#define PD 65                      // smem row pitch (floats)
#define ATT_SMEM ((BQ + BK + BK + BQ) * PD * 4)   // Qs,Ks,Vs,Ps = 99840 bytes

__global__ __launch_bounds__(128) void attn_kernel(
    const float* __restrict__ Qg, const float* __restrict__ Kg,
    const float* __restrict__ Vg, float* __restrict__ Og)
{
    extern __shared__ float sm[];
    float* Qs = sm;                 // [BQ][PD]
    float* Ks = Qs + BQ * PD;       // [BK][PD]
    float* Vs = Ks + BK * PD;       // [BK][PD]
    float* Ps = Vs + BK * PD;       // [BQ][PD]

    const int qb = blockIdx.x;
    const int h  = blockIdx.y;
    const int b  = blockIdx.z;
    const int tid = threadIdx.x;
    const int tx = tid & 7;         // col group 0..7  (8 cols each)
    const int ty = tid >> 3;        // row group 0..15 (8 rows each)

    const float scale = 0.125f;     // 1/sqrt(64)

    // Load Q tile (pre-scaled). 128 rows x 64 floats = 2048 float4.
    {
        const float* base = Qg + ((long)(b * SEQ + qb * BQ)) * NX + h * HD;
#pragma unroll
        for (int t = 0; t < 16; ++t) {
            int id = tid + t * 128;
            int r = id >> 4;
            int d4 = (id & 15) * 4;
            float4 v = *(const float4*)(base + (long)r * NX + d4);
            Qs[r * PD + d4 + 0] = v.x * scale;
            Qs[r * PD + d4 + 1] = v.y * scale;
            Qs[r * PD + d4 + 2] = v.z * scale;
            Qs[r * PD + d4 + 3] = v.w * scale;
        }
    }
    __syncthreads();

    float m_i[8], l_i[8], O[8][8];
#pragma unroll
    for (int i = 0; i < 8; ++i) {
        m_i[i] = -3.0e38f;
        l_i[i] = 0.0f;
#pragma unroll
        for (int j = 0; j < 8; ++j) O[i][j] = 0.0f;
    }

    const int nkb = 2 * qb + 2;     // causal: only blocks up to the diagonal

    for (int kb = 0; kb < nkb; ++kb) {
        __syncthreads();  // prior PV reads of Vs done before overwrite

        // Load K and V tiles: 64 rows x 64 floats = 1024 float4 each.
        {
            const float* kbase = Kg + ((long)(b * SEQ + kb * BK)) * NX + h * HD;
            const float* vbase = Vg + ((long)(b * SEQ + kb * BK)) * NX + h * HD;
#pragma unroll
            for (int t = 0; t < 8; ++t) {
                int id = tid + t * 128;
                int r = id >> 4;
                int d4 = (id & 15) * 4;
                float4 kv = *(const float4*)(kbase + (long)r * NX + d4);
                float4 vv = *(const float4*)(vbase + (long)r * NX + d4);
                Ks[r * PD + d4 + 0] = kv.x; Ks[r * PD + d4 + 1] = kv.y;
                Ks[r * PD + d4 + 2] = kv.z; Ks[r * PD + d4 + 3] = kv.w;
                Vs[r * PD + d4 + 0] = vv.x; Vs[r * PD + d4 + 1] = vv.y;
                Vs[r * PD + d4 + 2] = vv.z; Vs[r * PD + d4 + 3] = vv.w;
            }
        }
        __syncthreads();

        // S = Q K^T (scaled already)
        float s[8][8];
#pragma unroll
        for (int i = 0; i < 8; ++i)
#pragma unroll
            for (int j = 0; j < 8; ++j) s[i][j] = 0.0f;

#pragma unroll 4
        for (int d = 0; d < HD; ++d) {
            float qv[8], kv[8];
#pragma unroll
            for (int i = 0; i < 8; ++i) qv[i] = Qs[(ty * 8 + i) * PD + d];
#pragma unroll
            for (int j = 0; j < 8; ++j) kv[j] = Ks[(tx * 8 + j) * PD + d];
#pragma unroll
            for (int i = 0; i < 8; ++i)
#pragma unroll
                for (int j = 0; j < 8; ++j)
                    s[i][j] = fmaf(qv[i], kv[j], s[i][j]);
        }

        // Causal mask (reference uses exactly -10000.0 pre-softmax)
        if (kb >= 2 * qb) {
            const int r0 = qb * BQ + ty * 8;
            const int c0 = kb * BK + tx * 8;
#pragma unroll
            for (int i = 0; i < 8; ++i)
#pragma unroll
                for (int j = 0; j < 8; ++j)
                    if (c0 + j > r0 + i) s[i][j] = -10000.0f;
        }

        // Row max across the 8x8 tile, then across the 8 tx lanes
        float rm[8];
#pragma unroll
        for (int i = 0; i < 8; ++i) {
            float m = s[i][0];
#pragma unroll
            for (int j = 1; j < 8; ++j) m = fmaxf(m, s[i][j]);
            rm[i] = m;
        }
#pragma unroll
        for (int off = 1; off < 8; off <<= 1)
#pragma unroll
            for (int i = 0; i < 8; ++i)
                rm[i] = fmaxf(rm[i], __shfl_xor_sync(0xffffffffu, rm[i], off));

        float alpha[8], rs[8];
#pragma unroll
        for (int i = 0; i < 8; ++i) {
            float mn = fmaxf(m_i[i], rm[i]);
            alpha[i] = __expf(m_i[i] - mn);
            m_i[i] = mn;
            rs[i] = 0.0f;
        }

        // P = exp(S - m), stage into smem for the PV product
#pragma unroll
        for (int i = 0; i < 8; ++i) {
            float* prow = Ps + (ty * 8 + i) * PD + tx * 8;
#pragma unroll
            for (int j = 0; j < 8; ++j) {
                float p = __expf(s[i][j] - m_i[i]);
                prow[j] = p;
                rs[i] += p;
            }
        }
#pragma unroll
        for (int off = 1; off < 8; off <<= 1)
#pragma unroll
            for (int i = 0; i < 8; ++i)
                rs[i] += __shfl_xor_sync(0xffffffffu, rs[i], off);

#pragma unroll
        for (int i = 0; i < 8; ++i) {
            l_i[i] = l_i[i] * alpha[i] + rs[i];
#pragma unroll
            for (int j = 0; j < 8; ++j) O[i][j] *= alpha[i];
        }

        __syncwarp();   // Ps written & read within the same warp's ty-group

        // O += P @ V
#pragma unroll 4
        for (int c = 0; c < BK; ++c) {
            float pv[8], vv[8];
#pragma unroll
            for (int i = 0; i < 8; ++i) pv[i] = Ps[(ty * 8 + i) * PD + c];
#pragma unroll
            for (int j = 0; j < 8; ++j) vv[j] = Vs[c * PD + tx * 8 + j];
#pragma unroll
            for (int i = 0; i < 8; ++i)
#pragma unroll
                for (int j = 0; j < 8; ++j)
                    O[i][j] = fmaf(pv[i], vv[j], O[i][j]);
        }
    }

    // Normalize and write merged-head output: [B, S, NX]
#pragma unroll
    for (int i = 0; i < 8; ++i) {
        float inv = 1.0f / l_i[i];
        float* op = Og + ((long)(b * SEQ + qb * BQ + ty * 8 + i)) * NX
                       + h * HD + tx * 8;
#pragma unroll
        for (int j = 0; j < 8; ++j) op[j] = O[i][j] * inv;
    }
}

// ---------------------------------------------------------------------------
// Launch
// ---------------------------------------------------------------------------
extern "C" void kernel_launch(void* const* d_in, const int* in_sizes, int n_in,
                              void* d_out, int out_size)
{
    const float* x     = (const float*)d_in[0];
    const float* query = (const float*)d_in[1];
    const float* attw  = (const float*)d_in[2];   // [1024, 3072]
    const float* attb  = (const float*)d_in[3];   // [3072]
    const float* projw = (const float*)d_in[4];   // [1024, 1024]
    const float* projb = (const float*)d_in[5];   // [1024]
    float* out = (float*)d_out;

    float *qb_, *kb_, *vb_, *ab_;
    cudaGetSymbolAddress((void**)&qb_, g_q);
    cudaGetSymbolAddress((void**)&kb_, g_k);
    cudaGetSymbolAddress((void**)&vb_, g_v);
    cudaGetSymbolAddress((void**)&ab_, g_a);

    cudaFuncSetAttribute(attn_kernel,
                         cudaFuncAttributeMaxDynamicSharedMemorySize, ATT_SMEM);

    const int M = BSZ * SEQ;          // 8192
    dim3 gg(NX / 128, M / 128);       // (8, 64)

    // q = query @ W[:, 0:1024] + b[0:1024]
    sgemm_bias_kernel<<<gg, 256>>>(query, attw + 0 * NX, attb + 0 * NX, qb_,
                                   M, NX, NX, 3 * NX, NX);
    // k = x @ W[:, 1024:2048] + b[1024:2048]
    sgemm_bias_kernel<<<gg, 256>>>(x, attw + 1 * NX, attb + 1 * NX, kb_,
                                   M, NX, NX, 3 * NX, NX);
    // v = x @ W[:, 2048:3072] + b[2048:3072]
    sgemm_bias_kernel<<<gg, 256>>>(x, attw + 2 * NX, attb + 2 * NX, vb_,
                                   M, NX, NX, 3 * NX, NX);

    // attention -> merged heads in g_a
    attn_kernel<<<dim3(SEQ / BQ, NH, BSZ), 128, ATT_SMEM>>>(qb_, kb_, vb_, ab_);

    // out = a @ c_proj_w + c_proj_b
    sgemm_bias_kernel<<<gg, 256>>>(ab_, projw, projb, out,
                                   M, NX, NX, NX, NX);
}

// round 2
// speedup vs baseline: 1.6371x; 1.6371x over previous
#include <cuda_runtime.h>
#include <cstdint>

// Problem constants
#define BSZ 8
#define SEQ 1024
#define NX  1024
#define NH  16
#define HD  64

#define GELEMS (8u * 1024u * 1024u)  // 8*1024*1024 floats per scratch buffer

__device__ float g_q[GELEMS];
__device__ float g_k[GELEMS];
__device__ float g_v[GELEMS];
__device__ float g_a[GELEMS];

// ---------------------------------------------------------------------------
// tf32 helpers
// ---------------------------------------------------------------------------
__device__ __forceinline__ uint32_t f2tf32(float f) {
    uint32_t r;
    asm("cvt.rna.tf32.f32 %0, %1;" : "=r"(r) : "f"(f));
    return r;
}

__device__ __forceinline__ void mma_tf32(float c[4], const uint32_t a[4],
                                         const uint32_t b[2]) {
    asm volatile(
        "mma.sync.aligned.m16n8k8.row.col.f32.tf32.tf32.f32 "
        "{%0,%1,%2,%3}, {%4,%5,%6,%7}, {%8,%9}, {%0,%1,%2,%3};\n"
        : "+f"(c[0]), "+f"(c[1]), "+f"(c[2]), "+f"(c[3])
        : "r"(a[0]), "r"(a[1]), "r"(a[2]), "r"(a[3]), "r"(b[0]), "r"(b[1]));
}

// ---------------------------------------------------------------------------
// tf32 tensor-core GEMM with fused bias: C[M,N] = A[M,K] @ W (+ bias)
// A row-major lda=K; W row-major ldw (pre-offset to column block); C ldc.
// CTA tile 128x128, K-step 32, 256 threads = 8 warps (2m x 4n), warp 64x32.
// ---------------------------------------------------------------------------
#define SPITCH 132

__global__ __launch_bounds__(256) void tgemm_bias_kernel(
    const float* __restrict__ A, const float* __restrict__ W,
    const float* __restrict__ bias, float* __restrict__ C,
    int M, int N, int K, int ldw, int ldc)
{
    __shared__ uint32_t As[32 * SPITCH];   // As[k][m]  (tf32 bits)
    __shared__ uint32_t Bs[32 * SPITCH];   // Bs[k][n]

    const int tid  = threadIdx.x;
    const int wid  = tid >> 5;
    const int lane = tid & 31;
    const int gid  = lane >> 2;   // 0..7
    const int tg   = lane & 3;    // 0..3
    const int wm   = (wid & 1) * 64;   // warp m base within tile
    const int wn   = (wid >> 1) * 32;  // warp n base within tile

    const int m0 = blockIdx.y * 128;
    const int n0 = blockIdx.x * 128;

    // Global-load mappings (4 float4 each for A and B per thread)
    const int a_row = tid >> 1;              // rows 0..127 (2 thr/row)
    const int a_c4  = (tid & 1) * 16;        // col offset 0 or 16 (x4 floats each t)
    const int b_row = tid >> 5;              // rows 0..7 (+8 per t)
    const int b_c4  = (tid & 31) * 4;        // col offset

    float acc[4][4][4];
#pragma unroll
    for (int i = 0; i < 4; ++i)
#pragma unroll
        for (int j = 0; j < 4; ++j)
#pragma unroll
            for (int r = 0; r < 4; ++r) acc[i][j][r] = 0.0f;

    for (int k0 = 0; k0 < K; k0 += 32) {
        // Stage global loads in registers
        float4 av[4], bv[4];
        const float* Ap = A + (long)(m0 + a_row) * K + k0 + a_c4;
#pragma unroll
        for (int t = 0; t < 4; ++t) av[t] = *(const float4*)(Ap + t * 4);
#pragma unroll
        for (int t = 0; t < 4; ++t) {
            const float* Wp = W + (long)(k0 + b_row + t * 8) * ldw + n0 + b_c4;
            bv[t] = *(const float4*)Wp;
        }

        __syncthreads();
        // A: transposed scalar stores As[k][m]
#pragma unroll
        for (int t = 0; t < 4; ++t) {
            int kc = a_c4 + t * 4;
            As[(kc + 0) * SPITCH + a_row] = f2tf32(av[t].x);
            As[(kc + 1) * SPITCH + a_row] = f2tf32(av[t].y);
            As[(kc + 2) * SPITCH + a_row] = f2tf32(av[t].z);
            As[(kc + 3) * SPITCH + a_row] = f2tf32(av[t].w);
        }
        // B: row-major vector stores Bs[k][n]
#pragma unroll
        for (int t = 0; t < 4; ++t) {
            uint32_t* p = &Bs[(b_row + t * 8) * SPITCH + b_c4];
            p[0] = f2tf32(bv[t].x); p[1] = f2tf32(bv[t].y);
            p[2] = f2tf32(bv[t].z); p[3] = f2tf32(bv[t].w);
        }
        __syncthreads();

#pragma unroll
        for (int k8 = 0; k8 < 4; ++k8) {
            const int kb = k8 * 8;
            uint32_t afr[4][4];
            uint32_t bfr[4][2];
#pragma unroll
            for (int mf = 0; mf < 4; ++mf) {
                int mrow = wm + mf * 16 + gid;
                afr[mf][0] = As[(kb + tg) * SPITCH + mrow];
                afr[mf][1] = As[(kb + tg) * SPITCH + mrow + 8];
                afr[mf][2] = As[(kb + tg + 4) * SPITCH + mrow];
                afr[mf][3] = As[(kb + tg + 4) * SPITCH + mrow + 8];
            }
#pragma unroll
            for (int nf = 0; nf < 4; ++nf) {
                int ncol = wn + nf * 8 + gid;
                bfr[nf][0] = Bs[(kb + tg) * SPITCH + ncol];
                bfr[nf][1] = Bs[(kb + tg + 4) * SPITCH + ncol];
            }
#pragma unroll
            for (int mf = 0; mf < 4; ++mf)
#pragma unroll
                for (int nf = 0; nf < 4; ++nf)
                    mma_tf32(acc[mf][nf], afr[mf], bfr[nf]);
        }
    }

    // Epilogue: bias + store (float2 per fragment row)
#pragma unroll
    for (int nf = 0; nf < 4; ++nf) {
        int col = n0 + wn + nf * 8 + tg * 2;
        float b0 = bias[col], b1 = bias[col + 1];
#pragma unroll
        for (int mf = 0; mf < 4; ++mf) {
            int row0 = m0 + wm + mf * 16 + gid;
            float2 v0 = make_float2(acc[mf][nf][0] + b0, acc[mf][nf][1] + b1);
            float2 v1 = make_float2(acc[mf][nf][2] + b0, acc[mf][nf][3] + b1);
            *(float2*)(C + (long)row0 * ldc + col)       = v0;
            *(float2*)(C + (long)(row0 + 8) * ldc + col) = v1;
        }
    }
}

// ---------------------------------------------------------------------------
// Flash attention, fp32 (unchanged from R1). q/k/v layout [B,S,H,HD]=[m,NX].
// ---------------------------------------------------------------------------
#define BQ 128
#define BK 64
#define PD 65
#define ATT_SMEM ((BQ + BK + BK + BQ) * PD * 4)

__global__ __launch_bounds__(128) void attn_kernel(
    const float* __restrict__ Qg, const float* __restrict__ Kg,
    const float* __restrict__ Vg, float* __restrict__ Og)
{
    extern __shared__ float sm[];
    float* Qs = sm;
    float* Ks = Qs + BQ * PD;
    float* Vs = Ks + BK * PD;
    float* Ps = Vs + BK * PD;

    const int qb = blockIdx.x;
    const int h  = blockIdx.y;
    const int b  = blockIdx.z;
    const int tid = threadIdx.x;
    const int tx = tid & 7;
    const int ty = tid >> 3;

    const float scale = 0.125f;

    {
        const float* base = Qg + ((long)(b * SEQ + qb * BQ)) * NX + h * HD;
#pragma unroll
        for (int t = 0; t < 16; ++t) {
            int id = tid + t * 128;
            int r = id >> 4;
            int d4 = (id & 15) * 4;
            float4 v = *(const float4*)(base + (long)r * NX + d4);
            Qs[r * PD + d4 + 0] = v.x * scale;
            Qs[r * PD + d4 + 1] = v.y * scale;
            Qs[r * PD + d4 + 2] = v.z * scale;
            Qs[r * PD + d4 + 3] = v.w * scale;
        }
    }
    __syncthreads();

    float m_i[8], l_i[8], O[8][8];
#pragma unroll
    for (int i = 0; i < 8; ++i) {
        m_i[i] = -3.0e38f;
        l_i[i] = 0.0f;
#pragma unroll
        for (int j = 0; j < 8; ++j) O[i][j] = 0.0f;
    }

    const int nkb = 2 * qb + 2;

    for (int kb = 0; kb < nkb; ++kb) {
        __syncthreads();
        {
            const float* kbase = Kg + ((long)(b * SEQ + kb * BK)) * NX + h * HD;
            const float* vbase = Vg + ((long)(b * SEQ + kb * BK)) * NX + h * HD;
#pragma unroll
            for (int t = 0; t < 8; ++t) {
                int id = tid + t * 128;
                int r = id >> 4;
                int d4 = (id & 15) * 4;
                float4 kv = *(const float4*)(kbase + (long)r * NX + d4);
                float4 vv = *(const float4*)(vbase + (long)r * NX + d4);
                Ks[r * PD + d4 + 0] = kv.x; Ks[r * PD + d4 + 1] = kv.y;
                Ks[r * PD + d4 + 2] = kv.z; Ks[r * PD + d4 + 3] = kv.w;
                Vs[r * PD + d4 + 0] = vv.x; Vs[r * PD + d4 + 1] = vv.y;
                Vs[r * PD + d4 + 2] = vv.z; Vs[r * PD + d4 + 3] = vv.w;
            }
        }
        __syncthreads();

        float s[8][8];
#pragma unroll
        for (int i = 0; i < 8; ++i)
#pragma unroll
            for (int j = 0; j < 8; ++j) s[i][j] = 0.0f;

#pragma unroll 4
        for (int d = 0; d < HD; ++d) {
            float qv[8], kv[8];
#pragma unroll
            for (int i = 0; i < 8; ++i) qv[i] = Qs[(ty * 8 + i) * PD + d];
#pragma unroll
            for (int j = 0; j < 8; ++j) kv[j] = Ks[(tx * 8 + j) * PD + d];
#pragma unroll
            for (int i = 0; i < 8; ++i)
#pragma unroll
                for (int j = 0; j < 8; ++j)
                    s[i][j] = fmaf(qv[i], kv[j], s[i][j]);
        }

        if (kb >= 2 * qb) {
            const int r0 = qb * BQ + ty * 8;
            const int c0 = kb * BK + tx * 8;
#pragma unroll
            for (int i = 0; i < 8; ++i)
#pragma unroll
                for (int j = 0; j < 8; ++j)
                    if (c0 + j > r0 + i) s[i][j] = -10000.0f;
        }

        float rm[8];
#pragma unroll
        for (int i = 0; i < 8; ++i) {
            float m = s[i][0];
#pragma unroll
            for (int j = 1; j < 8; ++j) m = fmaxf(m, s[i][j]);
            rm[i] = m;
        }
#pragma unroll
        for (int off = 1; off < 8; off <<= 1)
#pragma unroll
            for (int i = 0; i < 8; ++i)
                rm[i] = fmaxf(rm[i], __shfl_xor_sync(0xffffffffu, rm[i], off));

        float alpha[8], rs[8];
#pragma unroll
        for (int i = 0; i < 8; ++i) {
            float mn = fmaxf(m_i[i], rm[i]);
            alpha[i] = __expf(m_i[i] - mn);
            m_i[i] = mn;
            rs[i] = 0.0f;
        }

#pragma unroll
        for (int i = 0; i < 8; ++i) {
            float* prow = Ps + (ty * 8 + i) * PD + tx * 8;
#pragma unroll
            for (int j = 0; j < 8; ++j) {
                float p = __expf(s[i][j] - m_i[i]);
                prow[j] = p;
                rs[i] += p;
            }
        }
#pragma unroll
        for (int off = 1; off < 8; off <<= 1)
#pragma unroll
            for (int i = 0; i < 8; ++i)
                rs[i] += __shfl_xor_sync(0xffffffffu, rs[i], off);

#pragma unroll
        for (int i = 0; i < 8; ++i) {
            l_i[i] = l_i[i] * alpha[i] + rs[i];
#pragma unroll
            for (int j = 0; j < 8; ++j) O[i][j] *= alpha[i];
        }

        __syncwarp();

#pragma unroll 4
        for (int c = 0; c < BK; ++c) {
            float pv[8], vv[8];
#pragma unroll
            for (int i = 0; i < 8; ++i) pv[i] = Ps[(ty * 8 + i) * PD + c];
#pragma unroll
            for (int j = 0; j < 8; ++j) vv[j] = Vs[c * PD + tx * 8 + j];
#pragma unroll
            for (int i = 0; i < 8; ++i)
#pragma unroll
                for (int j = 0; j < 8; ++j)
                    O[i][j] = fmaf(pv[i], vv[j], O[i][j]);
        }
    }

#pragma unroll
    for (int i = 0; i < 8; ++i) {
        float inv = 1.0f / l_i[i];
        float* op = Og + ((long)(b * SEQ + qb * BQ + ty * 8 + i)) * NX
                       + h * HD + tx * 8;
#pragma unroll
        for (int j = 0; j < 8; ++j) op[j] = O[i][j] * inv;
    }
}

// ---------------------------------------------------------------------------
// Launch
// ---------------------------------------------------------------------------
extern "C" void kernel_launch(void* const* d_in, const int* in_sizes, int n_in,
                              void* d_out, int out_size)
{
    const float* x     = (const float*)d_in[0];
    const float* query = (const float*)d_in[1];
    const float* attw  = (const float*)d_in[2];   // [1024, 3072]
    const float* attb  = (const float*)d_in[3];   // [3072]
    const float* projw = (const float*)d_in[4];   // [1024, 1024]
    const float* projb = (const float*)d_in[5];   // [1024]
    float* out = (float*)d_out;

    float *qb_, *kb_, *vb_, *ab_;
    cudaGetSymbolAddress((void**)&qb_, g_q);
    cudaGetSymbolAddress((void**)&kb_, g_k);
    cudaGetSymbolAddress((void**)&vb_, g_v);
    cudaGetSymbolAddress((void**)&ab_, g_a);

    cudaFuncSetAttribute(attn_kernel,
                         cudaFuncAttributeMaxDynamicSharedMemorySize, ATT_SMEM);

    const int M = BSZ * SEQ;          // 8192
    dim3 gg(NX / 128, M / 128);       // (8, 64)

    tgemm_bias_kernel<<<gg, 256>>>(query, attw + 0 * NX, attb + 0 * NX, qb_,
                                   M, NX, NX, 3 * NX, NX);
    tgemm_bias_kernel<<<gg, 256>>>(x, attw + 1 * NX, attb + 1 * NX, kb_,
                                   M, NX, NX, 3 * NX, NX);
    tgemm_bias_kernel<<<gg, 256>>>(x, attw + 2 * NX, attb + 2 * NX, vb_,
                                   M, NX, NX, 3 * NX, NX);

    attn_kernel<<<dim3(SEQ / BQ, NH, BSZ), 128, ATT_SMEM>>>(qb_, kb_, vb_, ab_);

    tgemm_bias_kernel<<<gg, 256>>>(ab_, projw, projb, out,
                                   M, NX, NX, NX, NX);
}

// round 3
// speedup vs baseline: 2.3025x; 1.4065x over previous
#include <cuda_runtime.h>
#include <cstdint>

// Problem constants
#define BSZ 8
#define SEQ 1024
#define NX  1024
#define NH  16
#define HD  64

#define GELEMS (8u * 1024u * 1024u)

__device__ float g_q[GELEMS];
__device__ float g_k[GELEMS];
__device__ float g_v[GELEMS];
__device__ float g_a[GELEMS];

// ---------------------------------------------------------------------------
// tf32 helpers
// ---------------------------------------------------------------------------
__device__ __forceinline__ uint32_t f2tf32(float f) {
    uint32_t r;
    asm("cvt.rna.tf32.f32 %0, %1;" : "=r"(r) : "f"(f));
    return r;
}

__device__ __forceinline__ void mma_tf32(float c[4], const uint32_t a[4],
                                         const uint32_t b[2]) {
    asm volatile(
        "mma.sync.aligned.m16n8k8.row.col.f32.tf32.tf32.f32 "
        "{%0,%1,%2,%3}, {%4,%5,%6,%7}, {%8,%9}, {%0,%1,%2,%3};\n"
        : "+f"(c[0]), "+f"(c[1]), "+f"(c[2]), "+f"(c[3])
        : "r"(a[0]), "r"(a[1]), "r"(a[2]), "r"(a[3]), "r"(b[0]), "r"(b[1]));
}

// ---------------------------------------------------------------------------
// tf32 tensor-core GEMM with fused bias (unchanged from R2)
// ---------------------------------------------------------------------------
#define SPITCH 132

__global__ __launch_bounds__(256) void tgemm_bias_kernel(
    const float* __restrict__ A, const float* __restrict__ W,
    const float* __restrict__ bias, float* __restrict__ C,
    int M, int N, int K, int ldw, int ldc)
{
    __shared__ uint32_t As[32 * SPITCH];
    __shared__ uint32_t Bs[32 * SPITCH];

    const int tid  = threadIdx.x;
    const int wid  = tid >> 5;
    const int lane = tid & 31;
    const int gid  = lane >> 2;
    const int tg   = lane & 3;
    const int wm   = (wid & 1) * 64;
    const int wn   = (wid >> 1) * 32;

    const int m0 = blockIdx.y * 128;
    const int n0 = blockIdx.x * 128;

    const int a_row = tid >> 1;
    const int a_c4  = (tid & 1) * 16;
    const int b_row = tid >> 5;
    const int b_c4  = (tid & 31) * 4;

    float acc[4][4][4];
#pragma unroll
    for (int i = 0; i < 4; ++i)
#pragma unroll
        for (int j = 0; j < 4; ++j)
#pragma unroll
            for (int r = 0; r < 4; ++r) acc[i][j][r] = 0.0f;

    for (int k0 = 0; k0 < K; k0 += 32) {
        float4 av[4], bv[4];
        const float* Ap = A + (long)(m0 + a_row) * K + k0 + a_c4;
#pragma unroll
        for (int t = 0; t < 4; ++t) av[t] = *(const float4*)(Ap + t * 4);
#pragma unroll
        for (int t = 0; t < 4; ++t) {
            const float* Wp = W + (long)(k0 + b_row + t * 8) * ldw + n0 + b_c4;
            bv[t] = *(const float4*)Wp;
        }

        __syncthreads();
#pragma unroll
        for (int t = 0; t < 4; ++t) {
            int kc = a_c4 + t * 4;
            As[(kc + 0) * SPITCH + a_row] = f2tf32(av[t].x);
            As[(kc + 1) * SPITCH + a_row] = f2tf32(av[t].y);
            As[(kc + 2) * SPITCH + a_row] = f2tf32(av[t].z);
            As[(kc + 3) * SPITCH + a_row] = f2tf32(av[t].w);
        }
#pragma unroll
        for (int t = 0; t < 4; ++t) {
            uint32_t* p = &Bs[(b_row + t * 8) * SPITCH + b_c4];
            p[0] = f2tf32(bv[t].x); p[1] = f2tf32(bv[t].y);
            p[2] = f2tf32(bv[t].z); p[3] = f2tf32(bv[t].w);
        }
        __syncthreads();

#pragma unroll
        for (int k8 = 0; k8 < 4; ++k8) {
            const int kb = k8 * 8;
            uint32_t afr[4][4];
            uint32_t bfr[4][2];
#pragma unroll
            for (int mf = 0; mf < 4; ++mf) {
                int mrow = wm + mf * 16 + gid;
                afr[mf][0] = As[(kb + tg) * SPITCH + mrow];
                afr[mf][1] = As[(kb + tg) * SPITCH + mrow + 8];
                afr[mf][2] = As[(kb + tg + 4) * SPITCH + mrow];
                afr[mf][3] = As[(kb + tg + 4) * SPITCH + mrow + 8];
            }
#pragma unroll
            for (int nf = 0; nf < 4; ++nf) {
                int ncol = wn + nf * 8 + gid;
                bfr[nf][0] = Bs[(kb + tg) * SPITCH + ncol];
                bfr[nf][1] = Bs[(kb + tg + 4) * SPITCH + ncol];
            }
#pragma unroll
            for (int mf = 0; mf < 4; ++mf)
#pragma unroll
                for (int nf = 0; nf < 4; ++nf)
                    mma_tf32(acc[mf][nf], afr[mf], bfr[nf]);
        }
    }

#pragma unroll
    for (int nf = 0; nf < 4; ++nf) {
        int col = n0 + wn + nf * 8 + tg * 2;
        float b0 = bias[col], b1 = bias[col + 1];
#pragma unroll
        for (int mf = 0; mf < 4; ++mf) {
            int row0 = m0 + wm + mf * 16 + gid;
            float2 v0 = make_float2(acc[mf][nf][0] + b0, acc[mf][nf][1] + b1);
            float2 v1 = make_float2(acc[mf][nf][2] + b0, acc[mf][nf][3] + b1);
            *(float2*)(C + (long)row0 * ldc + col)       = v0;
            *(float2*)(C + (long)(row0 + 8) * ldc + col) = v1;
        }
    }
}

// ---------------------------------------------------------------------------
// Flash attention with tf32 tensor-core MMA.
// q/k/v layout [B,S,H,HD] = [m, NX]. Grid (S/128, H, B), 256 threads (8 warps).
// Each warp owns 16 query rows. BK=64 keys per inner block.
// Smem: PQ[128][68] (Q staging, then P), Ks[64][68], Vs[64][68]  (tf32 bits).
// ---------------------------------------------------------------------------
#define BQ 128
#define BK 64
#define APD 68
#define ATT_SMEM ((BQ + BK + BK) * APD * 4)   // 69632 bytes

__global__ __launch_bounds__(256) void attn_kernel(
    const float* __restrict__ Qg, const float* __restrict__ Kg,
    const float* __restrict__ Vg, float* __restrict__ Og)
{
    extern __shared__ uint32_t sm4[];
    uint32_t* PQ = sm4;                 // [BQ][APD]  Q staging then P
    uint32_t* Ks = PQ + BQ * APD;       // [BK][APD]
    uint32_t* Vs = Ks + BK * APD;       // [BK][APD]

    const int qb = blockIdx.x;
    const int h  = blockIdx.y;
    const int b  = blockIdx.z;
    const int tid  = threadIdx.x;
    const int wid  = tid >> 5;
    const int lane = tid & 31;
    const int gid  = lane >> 2;   // 0..7
    const int tg   = lane & 3;    // 0..3

    const int r0 = wid * 16 + gid;   // this thread's rows within tile
    const int r1 = r0 + 8;
    const float scale = 0.125f;

    // ---- Stage Q (scaled, tf32) into PQ ----
    {
        const float* base = Qg + ((long)(b * SEQ + qb * BQ)) * NX + h * HD;
#pragma unroll
        for (int t = 0; t < 8; ++t) {
            int id = tid + t * 256;
            int r = id >> 4;
            int d4 = (id & 15) * 4;
            float4 v = *(const float4*)(base + (long)r * NX + d4);
            uint32_t* p = &PQ[r * APD + d4];
            p[0] = f2tf32(v.x * scale);
            p[1] = f2tf32(v.y * scale);
            p[2] = f2tf32(v.z * scale);
            p[3] = f2tf32(v.w * scale);
        }
    }
    __syncthreads();

    // ---- Hoist Q fragments to registers (PQ becomes dead -> reused for P) ----
    uint32_t qf[8][4];
#pragma unroll
    for (int ks = 0; ks < 8; ++ks) {
        int kc = ks * 8 + tg;
        qf[ks][0] = PQ[r0 * APD + kc];
        qf[ks][1] = PQ[r1 * APD + kc];
        qf[ks][2] = PQ[r0 * APD + kc + 4];
        qf[ks][3] = PQ[r1 * APD + kc + 4];
    }

    // Online softmax state for rows r0 (index 0) and r1 (index 1)
    float m_i[2] = {-3.0e38f, -3.0e38f};
    float l_i[2] = {0.0f, 0.0f};
    float O[8][4];
#pragma unroll
    for (int nf = 0; nf < 8; ++nf)
#pragma unroll
        for (int r = 0; r < 4; ++r) O[nf][r] = 0.0f;

    const int nkb = 2 * qb + 2;   // causal block count

    for (int kb = 0; kb < nkb; ++kb) {
        __syncthreads();   // prior iteration's K/V reads complete

        // ---- Stage K and V (tf32) ----
        {
            const float* kbase = Kg + ((long)(b * SEQ + kb * BK)) * NX + h * HD;
            const float* vbase = Vg + ((long)(b * SEQ + kb * BK)) * NX + h * HD;
#pragma unroll
            for (int t = 0; t < 4; ++t) {
                int id = tid + t * 256;
                int r = id >> 4;
                int d4 = (id & 15) * 4;
                float4 kv = *(const float4*)(kbase + (long)r * NX + d4);
                float4 vv = *(const float4*)(vbase + (long)r * NX + d4);
                uint32_t* pk = &Ks[r * APD + d4];
                pk[0] = f2tf32(kv.x); pk[1] = f2tf32(kv.y);
                pk[2] = f2tf32(kv.z); pk[3] = f2tf32(kv.w);
                uint32_t* pv = &Vs[r * APD + d4];
                pv[0] = f2tf32(vv.x); pv[1] = f2tf32(vv.y);
                pv[2] = f2tf32(vv.z); pv[3] = f2tf32(vv.w);
            }
        }
        __syncthreads();

        // ---- S = Q K^T via MMA:  s[nf] covers keys nf*8..nf*8+7 ----
        float s[8][4];
#pragma unroll
        for (int nf = 0; nf < 8; ++nf)
#pragma unroll
            for (int r = 0; r < 4; ++r) s[nf][r] = 0.0f;

#pragma unroll
        for (int ks = 0; ks < 8; ++ks) {
            int kc = ks * 8 + tg;
#pragma unroll
            for (int nf = 0; nf < 8; ++nf) {
                uint32_t bfr[2];
                int key = nf * 8 + gid;
                bfr[0] = Ks[key * APD + kc];
                bfr[1] = Ks[key * APD + kc + 4];
                mma_tf32(s[nf], qf[ks], bfr);
            }
        }

        // ---- Causal mask (only needed on the two diagonal blocks) ----
        if (kb >= 2 * qb) {
            const int grow0 = qb * BQ + r0;
            const int gcol0 = kb * BK + 2 * tg;
#pragma unroll
            for (int nf = 0; nf < 8; ++nf) {
                int c = gcol0 + nf * 8;
                if (c     > grow0)     s[nf][0] = -10000.0f;
                if (c + 1 > grow0)     s[nf][1] = -10000.0f;
                if (c     > grow0 + 8) s[nf][2] = -10000.0f;
                if (c + 1 > grow0 + 8) s[nf][3] = -10000.0f;
            }
        }

        // ---- Row max (across nf locally, then across the 4 tg lanes) ----
        float rm0 = s[0][0], rm1 = s[0][2];
#pragma unroll
        for (int nf = 0; nf < 8; ++nf) {
            rm0 = fmaxf(rm0, fmaxf(s[nf][0], s[nf][1]));
            rm1 = fmaxf(rm1, fmaxf(s[nf][2], s[nf][3]));
        }
        rm0 = fmaxf(rm0, __shfl_xor_sync(0xffffffffu, rm0, 1));
        rm0 = fmaxf(rm0, __shfl_xor_sync(0xffffffffu, rm0, 2));
        rm1 = fmaxf(rm1, __shfl_xor_sync(0xffffffffu, rm1, 1));
        rm1 = fmaxf(rm1, __shfl_xor_sync(0xffffffffu, rm1, 2));

        float mn0 = fmaxf(m_i[0], rm0);
        float mn1 = fmaxf(m_i[1], rm1);
        float alpha0 = __expf(m_i[0] - mn0);
        float alpha1 = __expf(m_i[1] - mn1);
        m_i[0] = mn0; m_i[1] = mn1;

        // ---- P = exp(S - m): store tf32 into PQ, accumulate row sums ----
        float ls0 = 0.0f, ls1 = 0.0f;
#pragma unroll
        for (int nf = 0; nf < 8; ++nf) {
            float p0 = __expf(s[nf][0] - mn0);
            float p1 = __expf(s[nf][1] - mn0);
            float p2 = __expf(s[nf][2] - mn1);
            float p3 = __expf(s[nf][3] - mn1);
            ls0 += p0 + p1;
            ls1 += p2 + p3;
            int col = nf * 8 + 2 * tg;
            *(uint2*)&PQ[r0 * APD + col] = make_uint2(f2tf32(p0), f2tf32(p1));
            *(uint2*)&PQ[r1 * APD + col] = make_uint2(f2tf32(p2), f2tf32(p3));
        }
        ls0 += __shfl_xor_sync(0xffffffffu, ls0, 1);
        ls0 += __shfl_xor_sync(0xffffffffu, ls0, 2);
        ls1 += __shfl_xor_sync(0xffffffffu, ls1, 1);
        ls1 += __shfl_xor_sync(0xffffffffu, ls1, 2);

        l_i[0] = l_i[0] * alpha0 + ls0;
        l_i[1] = l_i[1] * alpha1 + ls1;
#pragma unroll
        for (int nf = 0; nf < 8; ++nf) {
            O[nf][0] *= alpha0; O[nf][1] *= alpha0;
            O[nf][2] *= alpha1; O[nf][3] *= alpha1;
        }

        __syncwarp();   // P rows are warp-private; make stores visible

        // ---- O += P @ V via MMA: n-dim = head dim (64), k-dim = keys ----
#pragma unroll
        for (int ks = 0; ks < 8; ++ks) {
            int kc = ks * 8 + tg;
            uint32_t af[4];
            af[0] = PQ[r0 * APD + kc];
            af[1] = PQ[r1 * APD + kc];
            af[2] = PQ[r0 * APD + kc + 4];
            af[3] = PQ[r1 * APD + kc + 4];
#pragma unroll
            for (int nf = 0; nf < 8; ++nf) {
                uint32_t bfr[2];
                int d = nf * 8 + gid;
                bfr[0] = Vs[kc * APD + d];          // V[key=kc][d]
                bfr[1] = Vs[(kc + 4) * APD + d];
                mma_tf32(O[nf], af, bfr);
            }
        }
        __syncwarp();   // all lanes done reading P before next iter overwrites
    }

    // ---- Normalize and write merged-head output [B,S,NX] ----
    float inv0 = 1.0f / l_i[0];
    float inv1 = 1.0f / l_i[1];
    const long orow0 = (long)(b * SEQ + qb * BQ + r0);
#pragma unroll
    for (int nf = 0; nf < 8; ++nf) {
        int col = h * HD + nf * 8 + 2 * tg;
        *(float2*)(Og + orow0 * NX + col) =
            make_float2(O[nf][0] * inv0, O[nf][1] * inv0);
        *(float2*)(Og + (orow0 + 8) * NX + col) =
            make_float2(O[nf][2] * inv1, O[nf][3] * inv1);
    }
}

// ---------------------------------------------------------------------------
// Launch
// ---------------------------------------------------------------------------
extern "C" void kernel_launch(void* const* d_in, const int* in_sizes, int n_in,
                              void* d_out, int out_size)
{
    const float* x     = (const float*)d_in[0];
    const float* query = (const float*)d_in[1];
    const float* attw  = (const float*)d_in[2];
    const float* attb  = (const float*)d_in[3];
    const float* projw = (const float*)d_in[4];
    const float* projb = (const float*)d_in[5];
    float* out = (float*)d_out;

    float *qb_, *kb_, *vb_, *ab_;
    cudaGetSymbolAddress((void**)&qb_, g_q);
    cudaGetSymbolAddress((void**)&kb_, g_k);
    cudaGetSymbolAddress((void**)&vb_, g_v);
    cudaGetSymbolAddress((void**)&ab_, g_a);

    cudaFuncSetAttribute(attn_kernel,
                         cudaFuncAttributeMaxDynamicSharedMemorySize, ATT_SMEM);

    const int M = BSZ * SEQ;
    dim3 gg(NX / 128, M / 128);

    tgemm_bias_kernel<<<gg, 256>>>(query, attw + 0 * NX, attb + 0 * NX, qb_,
                                   M, NX, NX, 3 * NX, NX);
    tgemm_bias_kernel<<<gg, 256>>>(x, attw + 1 * NX, attb + 1 * NX, kb_,
                                   M, NX, NX, 3 * NX, NX);
    tgemm_bias_kernel<<<gg, 256>>>(x, attw + 2 * NX, attb + 2 * NX, vb_,
                                   M, NX, NX, 3 * NX, NX);

    attn_kernel<<<dim3(SEQ / BQ, NH, BSZ), 256, ATT_SMEM>>>(qb_, kb_, vb_, ab_);

    tgemm_bias_kernel<<<gg, 256>>>(ab_, projw, projb, out,
                                   M, NX, NX, NX, NX);
}